// round 5
// baseline (speedup 1.0000x reference)
#include <cuda_runtime.h>
#include <cuda_fp16.h>
#include <cstdint>
#include <cstddef>

// ---------------- problem constants ----------------
#define Bb   16
#define Ss   512
#define Ll   12
#define Hh   12
#define DHh  64
#define Dd   768
#define Mm   13
#define PH   144
#define GM   8192
#define GK   9216
#define GN   768

// ---------------- GEMM tiling ----------------
#define BM   128
#define BN   128
#define BK   64
#define KIT  (GK / BK)           // 144
#define STAGES 3
#define LDA_H 72                 // halfs per A smem row (64 + 8 pad)
#define LDB_H 136                // halfs per B smem row (128 + 8 pad)
#define SA_BYTES (BM * LDA_H * 2)         // 18432
#define SB_BYTES (BK * LDB_H * 2)         // 17408
#define STAGE_BYTES (SA_BYTES + SB_BYTES) // 35840
#define GEMM_DSMEM (STAGES * STAGE_BYTES) // 107520 -> 2 CTAs/SM

__device__ __half g_Ah[(size_t)GM * GK];   // mask-scaled fp16 A
__device__ __half g_Wh[(size_t)GK * GN];   // fp16 W_O (row-major [K][N])
__device__ float  g_bias[Bb * Dd];

// ============================ PTX helpers ============================
__device__ __forceinline__ uint32_t smem_u32(const void* p) {
    uint32_t a;
    asm("{ .reg .u64 t; cvta.to.shared.u64 t, %1; cvt.u32.u64 %0, t; }"
        : "=r"(a) : "l"(p));
    return a;
}
__device__ __forceinline__ void cpasync16(uint32_t dst, const void* src) {
    asm volatile("cp.async.cg.shared.global [%0], [%1], 16;"
                 :: "r"(dst), "l"(src));
}
__device__ __forceinline__ void cp_commit() {
    asm volatile("cp.async.commit_group;");
}
__device__ __forceinline__ void cp_wait1() {
    asm volatile("cp.async.wait_group 1;");
}
__device__ __forceinline__ void ldsm4(uint32_t* r, uint32_t addr) {
    asm volatile("ldmatrix.sync.aligned.m8n8.x4.shared.b16 {%0,%1,%2,%3}, [%4];"
                 : "=r"(r[0]), "=r"(r[1]), "=r"(r[2]), "=r"(r[3]) : "r"(addr));
}
__device__ __forceinline__ void ldsm4t(uint32_t* r, uint32_t addr) {
    asm volatile("ldmatrix.sync.aligned.m8n8.x4.trans.shared.b16 {%0,%1,%2,%3}, [%4];"
                 : "=r"(r[0]), "=r"(r[1]), "=r"(r[2]), "=r"(r[3]) : "r"(addr));
}
__device__ __forceinline__ void mma16816(float* c, const uint32_t* a,
                                         uint32_t b0, uint32_t b1) {
    asm volatile(
        "mma.sync.aligned.m16n8k16.row.col.f32.f16.f16.f32 "
        "{%0,%1,%2,%3}, {%4,%5,%6,%7}, {%8,%9}, {%0,%1,%2,%3};"
        : "+f"(c[0]), "+f"(c[1]), "+f"(c[2]), "+f"(c[3])
        : "r"(a[0]), "r"(a[1]), "r"(a[2]), "r"(a[3]), "r"(b0), "r"(b1));
}

// ============================ Kernel 1: bias ============================
// grid (Bb, 6): block (b, 128-wide d-chunk). 128 threads.
__global__ void __launch_bounds__(128)
bias_kernel(const float* __restrict__ mlp_mask,
            const float* __restrict__ attn_mask,
            const float* __restrict__ modal_mlp,
            const float* __restrict__ modal_attention,
            const float* __restrict__ post_bias) {
    int b = blockIdx.x;
    int d = blockIdx.y * 128 + threadIdx.x;
    float acc = 0.f;
#pragma unroll
    for (int m = 0; m < Mm; m++)
        acc += (1.f - mlp_mask[b * Mm + m]) * modal_mlp[m * Dd + d];
#pragma unroll 4
    for (int ph = 0; ph < PH; ph++)
        acc += (1.f - attn_mask[b * PH + ph]) * modal_attention[ph * Dd + d];
#pragma unroll
    for (int p = 0; p < Ll; p++)
        acc += post_bias[p * Dd + d];
    g_bias[b * Dd + d] = acc;
}

// ============================ Kernel 2: W_O -> fp16 ============================
__global__ void __launch_bounds__(256)
prep_w(const float* __restrict__ Wo) {
    size_t i = (size_t)blockIdx.x * 256 + threadIdx.x;  // float4 idx
    float4 v = reinterpret_cast<const float4*>(Wo)[i];
    __half2* dst = reinterpret_cast<__half2*>(g_Wh);
    dst[i * 2]     = __floats2half2_rn(v.x, v.y);
    dst[i * 2 + 1] = __floats2half2_rn(v.z, v.w);
}

// ============================ Kernel 3: A mask-scale -> fp16 ============================
__global__ void __launch_bounds__(256)
prep_a(const float* __restrict__ attn_stack, const float* __restrict__ attn_mask) {
    __shared__ float sM[PH];
    int bs = blockIdx.x;
    int b  = bs >> 9;
    int t  = threadIdx.x;
    if (t < PH) sM[t] = attn_mask[b * PH + t];
    __syncthreads();
    const float4* src = reinterpret_cast<const float4*>(attn_stack + (size_t)bs * GK);
    __half2* dst = reinterpret_cast<__half2*>(g_Ah + (size_t)bs * GK);
#pragma unroll
    for (int i = 0; i < 9; i++) {
        int idx = t + 256 * i;            // 0..2303 float4 units
        float s = sM[idx >> 4];           // 16 float4 = 64 floats per head
        float4 v = src[idx];
        dst[idx * 2]     = __floats2half2_rn(v.x * s, v.y * s);
        dst[idx * 2 + 1] = __floats2half2_rn(v.z * s, v.w * s);
    }
}

// ============================ Kernel 4: mlp term ============================
__global__ void __launch_bounds__(192)
mlp_kernel(const float* __restrict__ mlp_stack,
           const float* __restrict__ mlp_mask,
           float* __restrict__ out) {
    int bs = blockIdx.x;
    int b  = bs >> 9;
    int t  = threadIdx.x;
    const float4* mp =
        reinterpret_cast<const float4*>(mlp_stack) + (size_t)bs * Mm * (Dd / 4);
    float4 acc = reinterpret_cast<const float4*>(g_bias)[b * (Dd / 4) + t];
#pragma unroll
    for (int m = 0; m < Mm; m++) {
        float w  = __ldg(&mlp_mask[b * Mm + m]);
        float4 v = mp[m * (Dd / 4) + t];
        acc.x += w * v.x; acc.y += w * v.y;
        acc.z += w * v.z; acc.w += w * v.w;
    }
    reinterpret_cast<float4*>(out)[(size_t)bs * (Dd / 4) + t] = acc;
}

// ============================ Kernel 5: fp16 mma.sync GEMM ============================
// out[M,N] += g_Ah[M,K] @ g_Wh[K,N]
// 128 threads = 4 warps (2x2), 64x64 warp tiles, 2 CTAs/SM.
__global__ void __launch_bounds__(128, 2)
attn_gemm(float* __restrict__ out) {
    extern __shared__ char smem[];
    const uint32_t s0 = smem_u32(smem);

    const int t    = threadIdx.x;
    const int lane = t & 31;
    const int wid  = t >> 5;
    const int wm   = wid >> 1;       // 0..1
    const int wn   = wid & 1;        // 0..1
    const int mRow0 = blockIdx.y * BM;
    const int nCol0 = blockIdx.x * BN;

    // ---- cp.async thread-invariant bases (128 threads) ----
    // A: 1024 chunks of 16B; thread handles chunk t + 128*i, i=0..7
    //    row = (t>>3) + 16*i, col halfs = (t&7)*8
    const __half* gA = g_Ah + (size_t)(mRow0 + (t >> 3)) * GK + (t & 7) * 8;
    const uint32_t sAw = s0 + (t >> 3) * (LDA_H * 2) + (t & 7) * 16;
    // B: 1024 chunks; row = (t>>4) + 8*i, col halfs = (t&15)*8
    const __half* gB = g_Wh + (size_t)(t >> 4) * GN + nCol0 + (t & 15) * 8;
    const uint32_t sBw = s0 + SA_BYTES + (t >> 4) * (LDB_H * 2) + (t & 15) * 16;

    auto load_stage = [&](int kt, int st) {
        uint32_t so = st * STAGE_BYTES;
        const __half* ga = gA + kt * BK;
#pragma unroll
        for (int i = 0; i < 8; i++)
            cpasync16(sAw + so + i * 16 * (LDA_H * 2), ga + (size_t)i * 16 * GK);
        const __half* gb = gB + (size_t)kt * BK * GN;
#pragma unroll
        for (int i = 0; i < 8; i++)
            cpasync16(sBw + so + i * 8 * (LDB_H * 2), gb + (size_t)i * 8 * GN);
        cp_commit();
    };

    // ---- ldmatrix bases ----
    // A: row = wm*64 + mi*16 + (lane&15); col halfs = ks*16 + (lane>>4)*8
    const uint32_t aBase = s0 + (wm * 64 + (lane & 15)) * (LDA_H * 2) + (lane >> 4) * 16;
    // B: row = ks*16 + (lane&15); col halfs = wn*64 + nj*16 + (lane>>4)*8
    const uint32_t bBase = s0 + SA_BYTES + (lane & 15) * (LDB_H * 2) + wn * 128 + (lane >> 4) * 16;

    float acc[4][8][4];
#pragma unroll
    for (int mi = 0; mi < 4; mi++)
#pragma unroll
        for (int nt = 0; nt < 8; nt++)
#pragma unroll
            for (int r = 0; r < 4; r++) acc[mi][nt][r] = 0.f;

    load_stage(0, 0);
    load_stage(1, 1);

    int st_c = 0;
    int st_l = 2;
    for (int kt = 0; kt < KIT; kt++) {
        cp_wait1();
        __syncthreads();
        if (kt + 2 < KIT) load_stage(kt + 2, st_l);
        else cp_commit();   // keep group-count semantics for wait_group 1

        const uint32_t so = st_c * STAGE_BYTES;
#pragma unroll
        for (int ks = 0; ks < 4; ks++) {
            uint32_t af[4][4];
#pragma unroll
            for (int mi = 0; mi < 4; mi++)
                ldsm4(af[mi], aBase + so + mi * 16 * (LDA_H * 2) + ks * 32);
            uint32_t bf[4][4];
#pragma unroll
            for (int nj = 0; nj < 4; nj++)
                ldsm4t(bf[nj], bBase + so + ks * 16 * (LDB_H * 2) + nj * 32);
#pragma unroll
            for (int mi = 0; mi < 4; mi++)
#pragma unroll
                for (int nt = 0; nt < 8; nt++)
                    mma16816(acc[mi][nt], af[mi],
                             bf[nt >> 1][(nt & 1) * 2], bf[nt >> 1][(nt & 1) * 2 + 1]);
        }
        st_c = (st_c == STAGES - 1) ? 0 : st_c + 1;
        st_l = (st_l == STAGES - 1) ? 0 : st_l + 1;
    }

    // ---- epilogue: out += acc ----
    const int g  = lane >> 2;
    const int tq = lane & 3;
#pragma unroll
    for (int mi = 0; mi < 4; mi++) {
        int row0 = mRow0 + wm * 64 + mi * 16 + g;
#pragma unroll
        for (int nt = 0; nt < 8; nt++) {
            int col = nCol0 + wn * 64 + nt * 8 + tq * 2;
            float2* p0 = reinterpret_cast<float2*>(out + (size_t)row0 * GN + col);
            float2 v0 = *p0;
            v0.x += acc[mi][nt][0]; v0.y += acc[mi][nt][1];
            *p0 = v0;
            float2* p1 = reinterpret_cast<float2*>(out + (size_t)(row0 + 8) * GN + col);
            float2 v1 = *p1;
            v1.x += acc[mi][nt][2]; v1.y += acc[mi][nt][3];
            *p1 = v1;
        }
    }
}

// ============================ launch ============================
static const float* find_in(void* const* d_in, const int* in_sizes, int n_in,
                            long long want) {
    for (int i = 0; i < n_in; i++)
        if ((long long)in_sizes[i] == want) return (const float*)d_in[i];
    return nullptr;
}

extern "C" void kernel_launch(void* const* d_in, const int* in_sizes, int n_in,
                              void* d_out, int out_size) {
    const float* mlp_stack       = find_in(d_in, in_sizes, n_in, (long long)Bb * Ss * Mm * Dd);
    const float* attn_stack      = find_in(d_in, in_sizes, n_in, (long long)Bb * Ss * Ll * Hh * DHh);
    const float* mlp_mask        = find_in(d_in, in_sizes, n_in, (long long)Bb * Mm);
    const float* attn_mask       = find_in(d_in, in_sizes, n_in, (long long)Bb * Ll * Hh);
    const float* modal_mlp       = find_in(d_in, in_sizes, n_in, (long long)Mm * Dd);
    const float* modal_attention = find_in(d_in, in_sizes, n_in, (long long)Ll * Hh * Dd);
    const float* W_O             = find_in(d_in, in_sizes, n_in, (long long)Ll * Hh * DHh * Dd);
    const float* post_bias       = find_in(d_in, in_sizes, n_in, (long long)Ll * Dd);
    float* out = (float*)d_out;

    static bool inited = false;
    if (!inited) {
        cudaFuncSetAttribute(attn_gemm,
                             cudaFuncAttributeMaxDynamicSharedMemorySize, GEMM_DSMEM);
        inited = true;
    }

    bias_kernel<<<dim3(Bb, Dd / 128), 128>>>(mlp_mask, attn_mask, modal_mlp,
                                             modal_attention, post_bias);
    prep_w<<<(GK * GN / 4) / 256, 256>>>(W_O);
    prep_a<<<GM, 256>>>(attn_stack, attn_mask);
    mlp_kernel<<<GM, Dd / 4>>>(mlp_stack, mlp_mask, out);
    dim3 ggrid(GN / BN, GM / BM);   // (6, 64)
    attn_gemm<<<ggrid, 128, GEMM_DSMEM>>>(out);
}

// round 6
// speedup vs baseline: 1.1093x; 1.1093x over previous
#include <cuda_runtime.h>
#include <cuda_fp16.h>
#include <cstdint>
#include <cstddef>

// ---------------- problem constants ----------------
#define Bb   16
#define Ss   512
#define Ll   12
#define Hh   12
#define DHh  64
#define Dd   768
#define Mm   13
#define PH   144
#define GM   8192
#define GK   9216
#define GN   768

// ---------------- GEMM tiling (R4 proven config) ----------------
#define BM   128
#define BN   128
#define BK   64
#define KIT  (GK / BK)           // 144
#define STAGES 3
#define LDA_H 72                 // halfs per A smem row (64 + 8 pad)
#define LDB_H 136                // halfs per B smem row (128 + 8 pad)
#define SA_BYTES (BM * LDA_H * 2)         // 18432
#define SB_BYTES (BK * LDB_H * 2)         // 17408
#define STAGE_BYTES (SA_BYTES + SB_BYTES) // 35840
#define GEMM_DSMEM (STAGES * STAGE_BYTES) // 107520 -> 2 CTAs/SM

__device__ __half g_Ah[(size_t)GM * GK];   // mask-scaled fp16 A
__device__ __half g_Wh[(size_t)GK * GN];   // fp16 W_O (row-major [K][N])
__device__ float  g_bias[Bb * Dd];

// ============================ PTX helpers ============================
__device__ __forceinline__ uint32_t smem_u32(const void* p) {
    uint32_t a;
    asm("{ .reg .u64 t; cvta.to.shared.u64 t, %1; cvt.u32.u64 %0, t; }"
        : "=r"(a) : "l"(p));
    return a;
}
__device__ __forceinline__ void cpasync16(uint32_t dst, const void* src) {
    asm volatile("cp.async.cg.shared.global [%0], [%1], 16;"
                 :: "r"(dst), "l"(src));
}
__device__ __forceinline__ void cp_commit() {
    asm volatile("cp.async.commit_group;");
}
__device__ __forceinline__ void cp_wait1() {
    asm volatile("cp.async.wait_group 1;");
}
__device__ __forceinline__ void ldsm4(uint32_t* r, uint32_t addr) {
    asm volatile("ldmatrix.sync.aligned.m8n8.x4.shared.b16 {%0,%1,%2,%3}, [%4];"
                 : "=r"(r[0]), "=r"(r[1]), "=r"(r[2]), "=r"(r[3]) : "r"(addr));
}
__device__ __forceinline__ void ldsm4t(uint32_t* r, uint32_t addr) {
    asm volatile("ldmatrix.sync.aligned.m8n8.x4.trans.shared.b16 {%0,%1,%2,%3}, [%4];"
                 : "=r"(r[0]), "=r"(r[1]), "=r"(r[2]), "=r"(r[3]) : "r"(addr));
}
__device__ __forceinline__ void mma16816(float* c, const uint32_t* a,
                                         uint32_t b0, uint32_t b1) {
    asm volatile(
        "mma.sync.aligned.m16n8k16.row.col.f32.f16.f16.f32 "
        "{%0,%1,%2,%3}, {%4,%5,%6,%7}, {%8,%9}, {%0,%1,%2,%3};"
        : "+f"(c[0]), "+f"(c[1]), "+f"(c[2]), "+f"(c[3])
        : "r"(a[0]), "r"(a[1]), "r"(a[2]), "r"(a[3]), "r"(b0), "r"(b1));
}

// ============================ Kernel 1: bias ============================
__global__ void __launch_bounds__(128)
bias_kernel(const float* __restrict__ mlp_mask,
            const float* __restrict__ attn_mask,
            const float* __restrict__ modal_mlp,
            const float* __restrict__ modal_attention,
            const float* __restrict__ post_bias) {
    int b = blockIdx.x;
    int d = blockIdx.y * 128 + threadIdx.x;
    float acc = 0.f;
#pragma unroll
    for (int m = 0; m < Mm; m++)
        acc += (1.f - mlp_mask[b * Mm + m]) * modal_mlp[m * Dd + d];
#pragma unroll 4
    for (int ph = 0; ph < PH; ph++)
        acc += (1.f - attn_mask[b * PH + ph]) * modal_attention[ph * Dd + d];
#pragma unroll
    for (int p = 0; p < Ll; p++)
        acc += post_bias[p * Dd + d];
    g_bias[b * Dd + d] = acc;
}

// ============================ Kernel 2: W_O -> fp16 ============================
__global__ void __launch_bounds__(256)
prep_w(const float* __restrict__ Wo) {
    size_t i = (size_t)blockIdx.x * 256 + threadIdx.x;
    float4 v = reinterpret_cast<const float4*>(Wo)[i];
    __half2* dst = reinterpret_cast<__half2*>(g_Wh);
    dst[i * 2]     = __floats2half2_rn(v.x, v.y);
    dst[i * 2 + 1] = __floats2half2_rn(v.z, v.w);
}

// ============================ Kernel 3: A mask-scale -> fp16 ============================
__global__ void __launch_bounds__(256)
prep_a(const float* __restrict__ attn_stack, const float* __restrict__ attn_mask) {
    __shared__ float sM[PH];
    int bs = blockIdx.x;
    int b  = bs >> 9;
    int t  = threadIdx.x;
    if (t < PH) sM[t] = attn_mask[b * PH + t];
    __syncthreads();
    const float4* src = reinterpret_cast<const float4*>(attn_stack + (size_t)bs * GK);
    __half2* dst = reinterpret_cast<__half2*>(g_Ah + (size_t)bs * GK);
#pragma unroll
    for (int i = 0; i < 9; i++) {
        int idx = t + 256 * i;
        float s = sM[idx >> 4];
        float4 v = src[idx];
        dst[idx * 2]     = __floats2half2_rn(v.x * s, v.y * s);
        dst[idx * 2 + 1] = __floats2half2_rn(v.z * s, v.w * s);
    }
}

// ============================ Kernel 4: fp16 GEMM + fused mlp epilogue ============================
// out[M,N] = g_Ah[M,K] @ g_Wh[K,N] + sum_m mask*mlp_stack + bias
// 256 threads = 8 warps (2x4), 64x32 warp tiles, 2 CTAs/SM.
__global__ void __launch_bounds__(256, 2)
attn_gemm(const float* __restrict__ mlp_stack,
          const float* __restrict__ mlp_mask,
          float* __restrict__ out) {
    extern __shared__ char smem[];
    __shared__ float sMaskM[Mm];
    const uint32_t s0 = smem_u32(smem);

    const int t    = threadIdx.x;
    const int lane = t & 31;
    const int wid  = t >> 5;
    const int wm   = wid >> 2;       // 0..1
    const int wn   = wid & 3;        // 0..3
    const int mRow0 = blockIdx.y * BM;
    const int nCol0 = blockIdx.x * BN;
    const int b     = mRow0 >> 9;    // batch: BM=128 tiles within 512-row batches

    if (t < Mm) sMaskM[t] = mlp_mask[b * Mm + t];

    // ---- cp.async thread-invariant bases ----
    const __half* gA = g_Ah + (size_t)(mRow0 + (t >> 3)) * GK + (t & 7) * 8;
    const uint32_t sAw = s0 + (t >> 3) * (LDA_H * 2) + (t & 7) * 16;
    const __half* gB = g_Wh + (size_t)(t >> 4) * GN + nCol0 + (t & 15) * 8;
    const uint32_t sBw = s0 + SA_BYTES + (t >> 4) * (LDB_H * 2) + (t & 15) * 16;

    auto load_stage = [&](int kt, int st) {
        uint32_t so = st * STAGE_BYTES;
        const __half* ga = gA + kt * BK;
#pragma unroll
        for (int i = 0; i < 4; i++)
            cpasync16(sAw + so + i * 32 * (LDA_H * 2), ga + (size_t)i * 32 * GK);
        const __half* gb = gB + (size_t)kt * BK * GN;
#pragma unroll
        for (int i = 0; i < 4; i++)
            cpasync16(sBw + so + i * 16 * (LDB_H * 2), gb + (size_t)i * 16 * GN);
        cp_commit();
    };

    // ---- ldmatrix bases ----
    const uint32_t aBase = s0 + (wm * 64 + (lane & 15)) * (LDA_H * 2) + (lane >> 4) * 16;
    const uint32_t bBase = s0 + SA_BYTES + (lane & 15) * (LDB_H * 2) + wn * 64 + (lane >> 4) * 16;

    float acc[4][4][4];
#pragma unroll
    for (int mi = 0; mi < 4; mi++)
#pragma unroll
        for (int nt = 0; nt < 4; nt++)
#pragma unroll
            for (int r = 0; r < 4; r++) acc[mi][nt][r] = 0.f;

    load_stage(0, 0);
    load_stage(1, 1);

    int st_c = 0;
    int st_l = 2;
    for (int kt = 0; kt < KIT; kt++) {
        cp_wait1();
        __syncthreads();
        if (kt + 2 < KIT) load_stage(kt + 2, st_l);
        else cp_commit();   // keep group-count semantics for wait_group 1

        const uint32_t so = st_c * STAGE_BYTES;
#pragma unroll
        for (int ks = 0; ks < 4; ks++) {
            uint32_t af[4][4];
#pragma unroll
            for (int mi = 0; mi < 4; mi++)
                ldsm4(af[mi], aBase + so + mi * 16 * (LDA_H * 2) + ks * 32);
            uint32_t bf[2][4];
#pragma unroll
            for (int nj = 0; nj < 2; nj++)
                ldsm4t(bf[nj], bBase + so + ks * 16 * (LDB_H * 2) + nj * 32);
#pragma unroll
            for (int mi = 0; mi < 4; mi++)
#pragma unroll
                for (int nt = 0; nt < 4; nt++)
                    mma16816(acc[mi][nt], af[mi],
                             bf[nt >> 1][(nt & 1) * 2], bf[nt >> 1][(nt & 1) * 2 + 1]);
        }
        st_c = (st_c == STAGES - 1) ? 0 : st_c + 1;
        st_l = (st_l == STAGES - 1) ? 0 : st_l + 1;
    }

    // ---- fused epilogue: out = acc + bias + sum_m mask*mlp_stack (pure store) ----
    float wreg[Mm];
#pragma unroll
    for (int m = 0; m < Mm; m++) wreg[m] = sMaskM[m];
    const float* biasb = g_bias + b * Dd;

    const int g  = lane >> 2;
    const int tq = lane & 3;
#pragma unroll
    for (int mi = 0; mi < 4; mi++) {
        int r0 = mRow0 + wm * 64 + mi * 16 + g;
        const float* mp0 = mlp_stack + (size_t)r0 * Mm * Dd;        // row r0
        const float* mp1 = mlp_stack + (size_t)(r0 + 8) * Mm * Dd;  // row r0+8
#pragma unroll
        for (int nt = 0; nt < 4; nt++) {
            int col = nCol0 + wn * 32 + nt * 8 + tq * 2;
            float2 bz = *reinterpret_cast<const float2*>(biasb + col);
            float2 v0, v1;
            v0.x = acc[mi][nt][0] + bz.x; v0.y = acc[mi][nt][1] + bz.y;
            v1.x = acc[mi][nt][2] + bz.x; v1.y = acc[mi][nt][3] + bz.y;
#pragma unroll
            for (int m = 0; m < Mm; m++) {
                float2 u0 = __ldg(reinterpret_cast<const float2*>(mp0 + m * Dd + col));
                float2 u1 = __ldg(reinterpret_cast<const float2*>(mp1 + m * Dd + col));
                v0.x += wreg[m] * u0.x; v0.y += wreg[m] * u0.y;
                v1.x += wreg[m] * u1.x; v1.y += wreg[m] * u1.y;
            }
            *reinterpret_cast<float2*>(out + (size_t)r0 * GN + col)       = v0;
            *reinterpret_cast<float2*>(out + (size_t)(r0 + 8) * GN + col) = v1;
        }
    }
}

// ============================ launch ============================
static const float* find_in(void* const* d_in, const int* in_sizes, int n_in,
                            long long want) {
    for (int i = 0; i < n_in; i++)
        if ((long long)in_sizes[i] == want) return (const float*)d_in[i];
    return nullptr;
}

extern "C" void kernel_launch(void* const* d_in, const int* in_sizes, int n_in,
                              void* d_out, int out_size) {
    const float* mlp_stack       = find_in(d_in, in_sizes, n_in, (long long)Bb * Ss * Mm * Dd);
    const float* attn_stack      = find_in(d_in, in_sizes, n_in, (long long)Bb * Ss * Ll * Hh * DHh);
    const float* mlp_mask        = find_in(d_in, in_sizes, n_in, (long long)Bb * Mm);
    const float* attn_mask       = find_in(d_in, in_sizes, n_in, (long long)Bb * Ll * Hh);
    const float* modal_mlp       = find_in(d_in, in_sizes, n_in, (long long)Mm * Dd);
    const float* modal_attention = find_in(d_in, in_sizes, n_in, (long long)Ll * Hh * Dd);
    const float* W_O             = find_in(d_in, in_sizes, n_in, (long long)Ll * Hh * DHh * Dd);
    const float* post_bias       = find_in(d_in, in_sizes, n_in, (long long)Ll * Dd);
    float* out = (float*)d_out;

    static bool inited = false;
    if (!inited) {
        cudaFuncSetAttribute(attn_gemm,
                             cudaFuncAttributeMaxDynamicSharedMemorySize, GEMM_DSMEM);
        inited = true;
    }

    bias_kernel<<<dim3(Bb, Dd / 128), 128>>>(mlp_mask, attn_mask, modal_mlp,
                                             modal_attention, post_bias);
    prep_w<<<(GK * GN / 4) / 256, 256>>>(W_O);
    prep_a<<<GM, 256>>>(attn_stack, attn_mask);
    dim3 ggrid(GN / BN, GM / BM);   // (6, 64)
    attn_gemm<<<ggrid, 256, GEMM_DSMEM>>>(mlp_stack, mlp_mask, out);
}

// round 7
// speedup vs baseline: 1.2013x; 1.0829x over previous
#include <cuda_runtime.h>
#include <cuda_fp16.h>
#include <cstdint>
#include <cstddef>

// ---------------- problem constants ----------------
#define Bb   16
#define Ss   512
#define Ll   12
#define Hh   12
#define DHh  64
#define Dd   768
#define Mm   13
#define PH   144
#define GM   8192
#define GK   9216
#define GN   768

// ---------------- GEMM tiling ----------------
#define BM   128
#define BN   128
#define BK   64
#define KIT  (GK / BK)           // 144
#define STAGES 3
#define LDA_H 72                 // halfs per A smem row (64 + 8 pad)
#define LDB_H 136                // halfs per B smem row (128 + 8 pad)
#define SA_BYTES (BM * LDA_H * 2)         // 18432
#define SB_BYTES (BK * LDB_H * 2)         // 17408
#define STAGE_BYTES (SA_BYTES + SB_BYTES) // 35840
#define GEMM_DSMEM (STAGES * STAGE_BYTES) // 107520 -> 2 CTAs/SM

__device__ __half g_Ah[(size_t)GM * GK];   // mask-scaled fp16 A
__device__ __half g_Wh[(size_t)GK * GN];   // fp16 W_O (row-major [K][N])
__device__ float  g_bias[Bb * Dd];

// ============================ PTX helpers ============================
__device__ __forceinline__ uint32_t smem_u32(const void* p) {
    uint32_t a;
    asm("{ .reg .u64 t; cvta.to.shared.u64 t, %1; cvt.u32.u64 %0, t; }"
        : "=r"(a) : "l"(p));
    return a;
}
__device__ __forceinline__ void cpasync16(uint32_t dst, const void* src) {
    asm volatile("cp.async.cg.shared.global [%0], [%1], 16;"
                 :: "r"(dst), "l"(src));
}
__device__ __forceinline__ void cp_commit() {
    asm volatile("cp.async.commit_group;");
}
__device__ __forceinline__ void cp_wait1() {
    asm volatile("cp.async.wait_group 1;");
}
__device__ __forceinline__ void ldsm4(uint32_t* r, uint32_t addr) {
    asm volatile("ldmatrix.sync.aligned.m8n8.x4.shared.b16 {%0,%1,%2,%3}, [%4];"
                 : "=r"(r[0]), "=r"(r[1]), "=r"(r[2]), "=r"(r[3]) : "r"(addr));
}
__device__ __forceinline__ void ldsm4t(uint32_t* r, uint32_t addr) {
    asm volatile("ldmatrix.sync.aligned.m8n8.x4.trans.shared.b16 {%0,%1,%2,%3}, [%4];"
                 : "=r"(r[0]), "=r"(r[1]), "=r"(r[2]), "=r"(r[3]) : "r"(addr));
}
__device__ __forceinline__ void mma16816(float* c, const uint32_t* a,
                                         uint32_t b0, uint32_t b1) {
    asm volatile(
        "mma.sync.aligned.m16n8k16.row.col.f32.f16.f16.f32 "
        "{%0,%1,%2,%3}, {%4,%5,%6,%7}, {%8,%9}, {%0,%1,%2,%3};"
        : "+f"(c[0]), "+f"(c[1]), "+f"(c[2]), "+f"(c[3])
        : "r"(a[0]), "r"(a[1]), "r"(a[2]), "r"(a[3]), "r"(b0), "r"(b1));
}

// ============================ Kernel 1: bias ============================
__global__ void __launch_bounds__(128)
bias_kernel(const float* __restrict__ mlp_mask,
            const float* __restrict__ attn_mask,
            const float* __restrict__ modal_mlp,
            const float* __restrict__ modal_attention,
            const float* __restrict__ post_bias) {
    int b = blockIdx.x;
    int d = blockIdx.y * 128 + threadIdx.x;
    float acc = 0.f;
#pragma unroll
    for (int m = 0; m < Mm; m++)
        acc += (1.f - mlp_mask[b * Mm + m]) * modal_mlp[m * Dd + d];
#pragma unroll 4
    for (int ph = 0; ph < PH; ph++)
        acc += (1.f - attn_mask[b * PH + ph]) * modal_attention[ph * Dd + d];
#pragma unroll
    for (int p = 0; p < Ll; p++)
        acc += post_bias[p * Dd + d];
    g_bias[b * Dd + d] = acc;
}

// ============================ Kernel 2: W_O -> fp16 ============================
__global__ void __launch_bounds__(256)
prep_w(const float* __restrict__ Wo) {
    size_t i = (size_t)blockIdx.x * 256 + threadIdx.x;
    float4 v = reinterpret_cast<const float4*>(Wo)[i];
    __half2* dst = reinterpret_cast<__half2*>(g_Wh);
    dst[i * 2]     = __floats2half2_rn(v.x, v.y);
    dst[i * 2 + 1] = __floats2half2_rn(v.z, v.w);
}

// ============================ Kernel 3: A mask-scale -> fp16 ============================
__global__ void __launch_bounds__(256)
prep_a(const float* __restrict__ attn_stack, const float* __restrict__ attn_mask) {
    __shared__ float sM[PH];
    int bs = blockIdx.x;
    int b  = bs >> 9;
    int t  = threadIdx.x;
    if (t < PH) sM[t] = attn_mask[b * PH + t];
    __syncthreads();
    const float4* src = reinterpret_cast<const float4*>(attn_stack + (size_t)bs * GK);
    __half2* dst = reinterpret_cast<__half2*>(g_Ah + (size_t)bs * GK);
#pragma unroll
    for (int i = 0; i < 9; i++) {
        int idx = t + 256 * i;
        float s = sM[idx >> 4];
        float4 v = src[idx];
        dst[idx * 2]     = __floats2half2_rn(v.x * s, v.y * s);
        dst[idx * 2 + 1] = __floats2half2_rn(v.z * s, v.w * s);
    }
}

// ============================ Kernel 4: mlp term ============================
__global__ void __launch_bounds__(192)
mlp_kernel(const float* __restrict__ mlp_stack,
           const float* __restrict__ mlp_mask,
           float* __restrict__ out) {
    int bs = blockIdx.x;
    int b  = bs >> 9;
    int t  = threadIdx.x;
    const float4* mp =
        reinterpret_cast<const float4*>(mlp_stack) + (size_t)bs * Mm * (Dd / 4);
    float4 acc = reinterpret_cast<const float4*>(g_bias)[b * (Dd / 4) + t];
#pragma unroll
    for (int m = 0; m < Mm; m++) {
        float w  = __ldg(&mlp_mask[b * Mm + m]);
        float4 v = mp[m * (Dd / 4) + t];
        acc.x += w * v.x; acc.y += w * v.y;
        acc.z += w * v.z; acc.w += w * v.w;
    }
    reinterpret_cast<float4*>(out)[(size_t)bs * (Dd / 4) + t] = acc;
}

// ============================ Kernel 5: fp16 mma.sync GEMM ============================
// out[M,N] += g_Ah[M,K] @ g_Wh[K,N]
// 512 threads = 16 warps (4x4), 32x32 warp tiles, 2 CTAs/SM (32 warps/SM).
__global__ void __launch_bounds__(512, 2)
attn_gemm(float* __restrict__ out) {
    extern __shared__ char smem[];
    const uint32_t s0 = smem_u32(smem);

    const int t    = threadIdx.x;
    const int lane = t & 31;
    const int wid  = t >> 5;
    const int wm   = wid >> 2;       // 0..3
    const int wn   = wid & 3;        // 0..3
    const int mRow0 = blockIdx.y * BM;
    const int nCol0 = blockIdx.x * BN;

    // ---- cp.async thread-invariant bases (512 threads, 2 chunks each per buf) ----
    // A: 1024 chunks of 16B; chunk c = t + 512*i -> row (t>>3)+64*i, colchunk t&7
    const __half* gA = g_Ah + (size_t)(mRow0 + (t >> 3)) * GK + (t & 7) * 8;
    const uint32_t sAw = s0 + (t >> 3) * (LDA_H * 2) + (t & 7) * 16;
    // B: 1024 chunks; chunk c = t + 512*i -> row (t>>4)+32*i, colchunk t&15
    const __half* gB = g_Wh + (size_t)(t >> 4) * GN + nCol0 + (t & 15) * 8;
    const uint32_t sBw = s0 + SA_BYTES + (t >> 4) * (LDB_H * 2) + (t & 15) * 16;

    auto load_stage = [&](int kt, int st) {
        uint32_t so = st * STAGE_BYTES;
        const __half* ga = gA + kt * BK;
#pragma unroll
        for (int i = 0; i < 2; i++)
            cpasync16(sAw + so + i * 64 * (LDA_H * 2), ga + (size_t)i * 64 * GK);
        const __half* gb = gB + (size_t)kt * BK * GN;
#pragma unroll
        for (int i = 0; i < 2; i++)
            cpasync16(sBw + so + i * 32 * (LDB_H * 2), gb + (size_t)i * 32 * GN);
        cp_commit();
    };

    // ---- ldmatrix bases ----
    // A: row = wm*32 + mi*16 + (lane&15); col halfs = ks*16 + (lane>>4)*8
    const uint32_t aBase = s0 + (wm * 32 + (lane & 15)) * (LDA_H * 2) + (lane >> 4) * 16;
    // B: row = ks*16 + (lane&15); col halfs = wn*32 + nj*16 + (lane>>4)*8
    const uint32_t bBase = s0 + SA_BYTES + (lane & 15) * (LDB_H * 2) + wn * 64 + (lane >> 4) * 16;

    float acc[2][4][4];
#pragma unroll
    for (int mi = 0; mi < 2; mi++)
#pragma unroll
        for (int nt = 0; nt < 4; nt++)
#pragma unroll
            for (int r = 0; r < 4; r++) acc[mi][nt][r] = 0.f;

    load_stage(0, 0);
    load_stage(1, 1);

    int st_c = 0;
    int st_l = 2;
    for (int kt = 0; kt < KIT; kt++) {
        cp_wait1();
        __syncthreads();
        if (kt + 2 < KIT) load_stage(kt + 2, st_l);
        else cp_commit();   // keep group-count semantics for wait_group 1

        const uint32_t so = st_c * STAGE_BYTES;
#pragma unroll
        for (int ks = 0; ks < 4; ks++) {
            uint32_t af[2][4];
#pragma unroll
            for (int mi = 0; mi < 2; mi++)
                ldsm4(af[mi], aBase + so + mi * 16 * (LDA_H * 2) + ks * 32);
            uint32_t bf[2][4];
#pragma unroll
            for (int nj = 0; nj < 2; nj++)
                ldsm4t(bf[nj], bBase + so + ks * 16 * (LDB_H * 2) + nj * 32);
#pragma unroll
            for (int mi = 0; mi < 2; mi++)
#pragma unroll
                for (int nt = 0; nt < 4; nt++)
                    mma16816(acc[mi][nt], af[mi],
                             bf[nt >> 1][(nt & 1) * 2], bf[nt >> 1][(nt & 1) * 2 + 1]);
        }
        st_c = (st_c == STAGES - 1) ? 0 : st_c + 1;
        st_l = (st_l == STAGES - 1) ? 0 : st_l + 1;
    }

    // ---- epilogue: out += acc ----
    const int g  = lane >> 2;
    const int tq = lane & 3;
#pragma unroll
    for (int mi = 0; mi < 2; mi++) {
        int row0 = mRow0 + wm * 32 + mi * 16 + g;
#pragma unroll
        for (int nt = 0; nt < 4; nt++) {
            int col = nCol0 + wn * 32 + nt * 8 + tq * 2;
            float2* p0 = reinterpret_cast<float2*>(out + (size_t)row0 * GN + col);
            float2 v0 = *p0;
            v0.x += acc[mi][nt][0]; v0.y += acc[mi][nt][1];
            *p0 = v0;
            float2* p1 = reinterpret_cast<float2*>(out + (size_t)(row0 + 8) * GN + col);
            float2 v1 = *p1;
            v1.x += acc[mi][nt][2]; v1.y += acc[mi][nt][3];
            *p1 = v1;
        }
    }
}

// ============================ launch ============================
static const float* find_in(void* const* d_in, const int* in_sizes, int n_in,
                            long long want) {
    for (int i = 0; i < n_in; i++)
        if ((long long)in_sizes[i] == want) return (const float*)d_in[i];
    return nullptr;
}

extern "C" void kernel_launch(void* const* d_in, const int* in_sizes, int n_in,
                              void* d_out, int out_size) {
    const float* mlp_stack       = find_in(d_in, in_sizes, n_in, (long long)Bb * Ss * Mm * Dd);
    const float* attn_stack      = find_in(d_in, in_sizes, n_in, (long long)Bb * Ss * Ll * Hh * DHh);
    const float* mlp_mask        = find_in(d_in, in_sizes, n_in, (long long)Bb * Mm);
    const float* attn_mask       = find_in(d_in, in_sizes, n_in, (long long)Bb * Ll * Hh);
    const float* modal_mlp       = find_in(d_in, in_sizes, n_in, (long long)Mm * Dd);
    const float* modal_attention = find_in(d_in, in_sizes, n_in, (long long)Ll * Hh * Dd);
    const float* W_O             = find_in(d_in, in_sizes, n_in, (long long)Ll * Hh * DHh * Dd);
    const float* post_bias       = find_in(d_in, in_sizes, n_in, (long long)Ll * Dd);
    float* out = (float*)d_out;

    static bool inited = false;
    if (!inited) {
        cudaFuncSetAttribute(attn_gemm,
                             cudaFuncAttributeMaxDynamicSharedMemorySize, GEMM_DSMEM);
        inited = true;
    }

    bias_kernel<<<dim3(Bb, Dd / 128), 128>>>(mlp_mask, attn_mask, modal_mlp,
                                             modal_attention, post_bias);
    prep_w<<<(GK * GN / 4) / 256, 256>>>(W_O);
    prep_a<<<GM, 256>>>(attn_stack, attn_mask);
    mlp_kernel<<<GM, Dd / 4>>>(mlp_stack, mlp_mask, out);
    dim3 ggrid(GN / BN, GM / BM);   // (6, 64)
    attn_gemm<<<ggrid, 512, GEMM_DSMEM>>>(out);
}

// round 8
// speedup vs baseline: 1.2555x; 1.0451x over previous
#include <cuda_runtime.h>
#include <cuda_fp16.h>
#include <cstdint>
#include <cstddef>

// ---------------- problem constants ----------------
#define Bb   16
#define Ss   512
#define Ll   12
#define Hh   12
#define DHh  64
#define Dd   768
#define Mm   13
#define PH   144
#define GM   8192
#define GK   9216
#define GN   768

// ---------------- GEMM tiling (R4 proven config) ----------------
#define BM   128
#define BN   128
#define BK   64
#define KIT  (GK / BK)           // 144
#define STAGES 3
#define LDA_H 72
#define LDB_H 136
#define SA_BYTES (BM * LDA_H * 2)         // 18432
#define SB_BYTES (BK * LDB_H * 2)         // 17408
#define STAGE_BYTES (SA_BYTES + SB_BYTES) // 35840
#define GEMM_DSMEM (STAGES * STAGE_BYTES) // 107520 -> 2 CTAs/SM

__device__ __half g_Ah[(size_t)GM * GK];    // mask-scaled fp16 A
__device__ __half g_Wh[(size_t)GK * GN];    // fp16 W_O (row-major [K][N])
__device__ float  g_bias[Bb * Dd];
__device__ float  g_mlpout[(size_t)GM * GN]; // mlp term + bias (scratch)

// ============================ PTX helpers ============================
__device__ __forceinline__ uint32_t smem_u32(const void* p) {
    uint32_t a;
    asm("{ .reg .u64 t; cvta.to.shared.u64 t, %1; cvt.u32.u64 %0, t; }"
        : "=r"(a) : "l"(p));
    return a;
}
__device__ __forceinline__ void cpasync16(uint32_t dst, const void* src) {
    asm volatile("cp.async.cg.shared.global [%0], [%1], 16;"
                 :: "r"(dst), "l"(src));
}
__device__ __forceinline__ void cp_commit() {
    asm volatile("cp.async.commit_group;");
}
__device__ __forceinline__ void cp_wait1() {
    asm volatile("cp.async.wait_group 1;");
}
__device__ __forceinline__ void ldsm4(uint32_t* r, uint32_t addr) {
    asm volatile("ldmatrix.sync.aligned.m8n8.x4.shared.b16 {%0,%1,%2,%3}, [%4];"
                 : "=r"(r[0]), "=r"(r[1]), "=r"(r[2]), "=r"(r[3]) : "r"(addr));
}
__device__ __forceinline__ void ldsm4t(uint32_t* r, uint32_t addr) {
    asm volatile("ldmatrix.sync.aligned.m8n8.x4.trans.shared.b16 {%0,%1,%2,%3}, [%4];"
                 : "=r"(r[0]), "=r"(r[1]), "=r"(r[2]), "=r"(r[3]) : "r"(addr));
}
__device__ __forceinline__ void mma16816(float* c, const uint32_t* a,
                                         uint32_t b0, uint32_t b1) {
    asm volatile(
        "mma.sync.aligned.m16n8k16.row.col.f32.f16.f16.f32 "
        "{%0,%1,%2,%3}, {%4,%5,%6,%7}, {%8,%9}, {%0,%1,%2,%3};"
        : "+f"(c[0]), "+f"(c[1]), "+f"(c[2]), "+f"(c[3])
        : "r"(a[0]), "r"(a[1]), "r"(a[2]), "r"(a[3]), "r"(b0), "r"(b1));
}

// ============================ Kernel 1: bias ============================
__global__ void __launch_bounds__(128)
bias_kernel(const float* __restrict__ mlp_mask,
            const float* __restrict__ attn_mask,
            const float* __restrict__ modal_mlp,
            const float* __restrict__ modal_attention,
            const float* __restrict__ post_bias) {
    int b = blockIdx.x;
    int d = blockIdx.y * 128 + threadIdx.x;
    float acc = 0.f;
#pragma unroll
    for (int m = 0; m < Mm; m++)
        acc += (1.f - mlp_mask[b * Mm + m]) * modal_mlp[m * Dd + d];
#pragma unroll 4
    for (int ph = 0; ph < PH; ph++)
        acc += (1.f - attn_mask[b * PH + ph]) * modal_attention[ph * Dd + d];
#pragma unroll
    for (int p = 0; p < Ll; p++)
        acc += post_bias[p * Dd + d];
    g_bias[b * Dd + d] = acc;
}

// ============================ Kernel 2: W_O -> fp16 ============================
__global__ void __launch_bounds__(256)
prep_w(const float* __restrict__ Wo) {
    size_t i = (size_t)blockIdx.x * 256 + threadIdx.x;
    float4 v = reinterpret_cast<const float4*>(Wo)[i];
    __half2* dst = reinterpret_cast<__half2*>(g_Wh);
    dst[i * 2]     = __floats2half2_rn(v.x, v.y);
    dst[i * 2 + 1] = __floats2half2_rn(v.z, v.w);
}

// ============================ Kernel 3: A mask-scale -> fp16 ============================
__global__ void __launch_bounds__(256)
prep_a(const float* __restrict__ attn_stack, const float* __restrict__ attn_mask) {
    __shared__ float sM[PH];
    int bs = blockIdx.x;
    int b  = bs >> 9;
    int t  = threadIdx.x;
    if (t < PH) sM[t] = attn_mask[b * PH + t];
    __syncthreads();
    const float4* src = reinterpret_cast<const float4*>(attn_stack + (size_t)bs * GK);
    __half2* dst = reinterpret_cast<__half2*>(g_Ah + (size_t)bs * GK);
#pragma unroll
    for (int i = 0; i < 9; i++) {
        int idx = t + 256 * i;
        float s = sM[idx >> 4];
        float4 v = src[idx];
        dst[idx * 2]     = __floats2half2_rn(v.x * s, v.y * s);
        dst[idx * 2 + 1] = __floats2half2_rn(v.z * s, v.w * s);
    }
}

// ============================ Kernel 4: mlp term -> scratch ============================
__global__ void __launch_bounds__(192)
mlp_kernel(const float* __restrict__ mlp_stack,
           const float* __restrict__ mlp_mask) {
    int bs = blockIdx.x;
    int b  = bs >> 9;
    int t  = threadIdx.x;
    const float4* mp =
        reinterpret_cast<const float4*>(mlp_stack) + (size_t)bs * Mm * (Dd / 4);
    float4 acc = reinterpret_cast<const float4*>(g_bias)[b * (Dd / 4) + t];
#pragma unroll
    for (int m = 0; m < Mm; m++) {
        float w  = __ldg(&mlp_mask[b * Mm + m]);
        float4 v = mp[m * (Dd / 4) + t];
        acc.x += w * v.x; acc.y += w * v.y;
        acc.z += w * v.z; acc.w += w * v.w;
    }
    reinterpret_cast<float4*>(g_mlpout)[(size_t)bs * (Dd / 4) + t] = acc;
}

// ============================ Kernel 5: final add ============================
__global__ void __launch_bounds__(256)
add_kernel(float* __restrict__ out) {
    size_t i = (size_t)blockIdx.x * 256 + threadIdx.x;   // float4 units
    float4 a = reinterpret_cast<float4*>(out)[i];
    float4 bz = reinterpret_cast<const float4*>(g_mlpout)[i];
    a.x += bz.x; a.y += bz.y; a.z += bz.z; a.w += bz.w;
    reinterpret_cast<float4*>(out)[i] = a;
}

// ============================ Kernel 6: fp16 mma.sync GEMM ============================
// out[M,N] = g_Ah[M,K] @ g_Wh[K,N]   (pure store)
// 256 threads = 8 warps (2x4), 64x32 warp tiles, 2 CTAs/SM.
__global__ void __launch_bounds__(256, 2)
attn_gemm(float* __restrict__ out) {
    extern __shared__ char smem[];
    const uint32_t s0 = smem_u32(smem);

    const int t    = threadIdx.x;
    const int lane = t & 31;
    const int wid  = t >> 5;
    const int wm   = wid >> 2;       // 0..1
    const int wn   = wid & 3;        // 0..3
    const int mRow0 = blockIdx.y * BM;
    const int nCol0 = blockIdx.x * BN;

    const __half* gA = g_Ah + (size_t)(mRow0 + (t >> 3)) * GK + (t & 7) * 8;
    const uint32_t sAw = s0 + (t >> 3) * (LDA_H * 2) + (t & 7) * 16;
    const __half* gB = g_Wh + (size_t)(t >> 4) * GN + nCol0 + (t & 15) * 8;
    const uint32_t sBw = s0 + SA_BYTES + (t >> 4) * (LDB_H * 2) + (t & 15) * 16;

    auto load_stage = [&](int kt, int st) {
        uint32_t so = st * STAGE_BYTES;
        const __half* ga = gA + kt * BK;
#pragma unroll
        for (int i = 0; i < 4; i++)
            cpasync16(sAw + so + i * 32 * (LDA_H * 2), ga + (size_t)i * 32 * GK);
        const __half* gb = gB + (size_t)kt * BK * GN;
#pragma unroll
        for (int i = 0; i < 4; i++)
            cpasync16(sBw + so + i * 16 * (LDB_H * 2), gb + (size_t)i * 16 * GN);
        cp_commit();
    };

    const uint32_t aBase = s0 + (wm * 64 + (lane & 15)) * (LDA_H * 2) + (lane >> 4) * 16;
    const uint32_t bBase = s0 + SA_BYTES + (lane & 15) * (LDB_H * 2) + wn * 64 + (lane >> 4) * 16;

    float acc[4][4][4];
#pragma unroll
    for (int mi = 0; mi < 4; mi++)
#pragma unroll
        for (int nt = 0; nt < 4; nt++)
#pragma unroll
            for (int r = 0; r < 4; r++) acc[mi][nt][r] = 0.f;

    load_stage(0, 0);
    load_stage(1, 1);

    int st_c = 0;
    int st_l = 2;
    for (int kt = 0; kt < KIT; kt++) {
        cp_wait1();
        __syncthreads();
        if (kt + 2 < KIT) load_stage(kt + 2, st_l);
        else cp_commit();

        const uint32_t so = st_c * STAGE_BYTES;
#pragma unroll
        for (int ks = 0; ks < 4; ks++) {
            uint32_t af[4][4];
#pragma unroll
            for (int mi = 0; mi < 4; mi++)
                ldsm4(af[mi], aBase + so + mi * 16 * (LDA_H * 2) + ks * 32);
            uint32_t bf[2][4];
#pragma unroll
            for (int nj = 0; nj < 2; nj++)
                ldsm4t(bf[nj], bBase + so + ks * 16 * (LDB_H * 2) + nj * 32);
#pragma unroll
            for (int mi = 0; mi < 4; mi++)
#pragma unroll
                for (int nt = 0; nt < 4; nt++)
                    mma16816(acc[mi][nt], af[mi],
                             bf[nt >> 1][(nt & 1) * 2], bf[nt >> 1][(nt & 1) * 2 + 1]);
        }
        st_c = (st_c == STAGES - 1) ? 0 : st_c + 1;
        st_l = (st_l == STAGES - 1) ? 0 : st_l + 1;
    }

    // ---- epilogue: pure store ----
    const int g  = lane >> 2;
    const int tq = lane & 3;
#pragma unroll
    for (int mi = 0; mi < 4; mi++) {
        int row0 = mRow0 + wm * 64 + mi * 16 + g;
#pragma unroll
        for (int nt = 0; nt < 4; nt++) {
            int col = nCol0 + wn * 32 + nt * 8 + tq * 2;
            float2 v0, v1;
            v0.x = acc[mi][nt][0]; v0.y = acc[mi][nt][1];
            v1.x = acc[mi][nt][2]; v1.y = acc[mi][nt][3];
            *reinterpret_cast<float2*>(out + (size_t)row0 * GN + col)       = v0;
            *reinterpret_cast<float2*>(out + (size_t)(row0 + 8) * GN + col) = v1;
        }
    }
}

// ============================ launch ============================
static const float* find_in(void* const* d_in, const int* in_sizes, int n_in,
                            long long want) {
    for (int i = 0; i < n_in; i++)
        if ((long long)in_sizes[i] == want) return (const float*)d_in[i];
    return nullptr;
}

extern "C" void kernel_launch(void* const* d_in, const int* in_sizes, int n_in,
                              void* d_out, int out_size) {
    const float* mlp_stack       = find_in(d_in, in_sizes, n_in, (long long)Bb * Ss * Mm * Dd);
    const float* attn_stack      = find_in(d_in, in_sizes, n_in, (long long)Bb * Ss * Ll * Hh * DHh);
    const float* mlp_mask        = find_in(d_in, in_sizes, n_in, (long long)Bb * Mm);
    const float* attn_mask       = find_in(d_in, in_sizes, n_in, (long long)Bb * Ll * Hh);
    const float* modal_mlp       = find_in(d_in, in_sizes, n_in, (long long)Mm * Dd);
    const float* modal_attention = find_in(d_in, in_sizes, n_in, (long long)Ll * Hh * Dd);
    const float* W_O             = find_in(d_in, in_sizes, n_in, (long long)Ll * Hh * DHh * Dd);
    const float* post_bias       = find_in(d_in, in_sizes, n_in, (long long)Ll * Dd);
    float* out = (float*)d_out;

    static cudaStream_t s2 = nullptr;
    static cudaEvent_t evFork = nullptr, evJoin = nullptr;
    static bool inited = false;
    if (!inited) {
        cudaFuncSetAttribute(attn_gemm,
                             cudaFuncAttributeMaxDynamicSharedMemorySize, GEMM_DSMEM);
        cudaStreamCreateWithFlags(&s2, cudaStreamNonBlocking);
        cudaEventCreateWithFlags(&evFork, cudaEventDisableTiming);
        cudaEventCreateWithFlags(&evJoin, cudaEventDisableTiming);
        inited = true;
    }

    // main stream: bias -> (fork) -> prep_w -> prep_a -> gemm -> (join) -> add
    bias_kernel<<<dim3(Bb, Dd / 128), 128>>>(mlp_mask, attn_mask, modal_mlp,
                                             modal_attention, post_bias);
    cudaEventRecord(evFork, 0);
    cudaStreamWaitEvent(s2, evFork, 0);

    // side stream: mlp term into scratch (overlaps prep + gemm)
    mlp_kernel<<<GM, Dd / 4, 0, s2>>>(mlp_stack, mlp_mask);
    cudaEventRecord(evJoin, s2);

    prep_w<<<(GK * GN / 4) / 256, 256>>>(W_O);
    prep_a<<<GM, 256>>>(attn_stack, attn_mask);
    dim3 ggrid(GN / BN, GM / BM);   // (6, 64)
    attn_gemm<<<ggrid, 256, GEMM_DSMEM>>>(out);

    cudaStreamWaitEvent(0, evJoin, 0);
    add_kernel<<<(GM * GN / 4) / 256, 256>>>(out);
}

// round 9
// speedup vs baseline: 1.2585x; 1.0024x over previous
#include <cuda_runtime.h>
#include <cuda_fp16.h>
#include <cstdint>
#include <cstddef>

// ---------------- problem constants ----------------
#define Bb   16
#define Ss   512
#define Ll   12
#define Hh   12
#define DHh  64
#define Dd   768
#define Mm   13
#define PH   144
#define GM   8192
#define GK   9216
#define GN   768

// ---------------- GEMM tiling (R4 proven config) ----------------
#define BM   128
#define BN   128
#define BK   64
#define KIT  (GK / BK)           // 144
#define STAGES 3
#define LDA_H 72
#define LDB_H 136
#define SA_BYTES (BM * LDA_H * 2)         // 18432
#define SB_BYTES (BK * LDB_H * 2)         // 17408
#define STAGE_BYTES (SA_BYTES + SB_BYTES) // 35840
#define GEMM_DSMEM (STAGES * STAGE_BYTES) // 107520 -> 2 CTAs/SM

__device__ __half g_Ah[(size_t)GM * GK];     // mask-scaled fp16 A
__device__ __half g_Wh[(size_t)GK * GN];     // fp16 W_O (row-major [K][N])
__device__ float  g_bias[Bb * Dd];
__device__ float  g_mlpout[(size_t)GM * GN]; // mlp term + bias (scratch)

// ============================ PTX helpers ============================
__device__ __forceinline__ uint32_t smem_u32(const void* p) {
    uint32_t a;
    asm("{ .reg .u64 t; cvta.to.shared.u64 t, %1; cvt.u32.u64 %0, t; }"
        : "=r"(a) : "l"(p));
    return a;
}
__device__ __forceinline__ void cpasync16(uint32_t dst, const void* src) {
    asm volatile("cp.async.cg.shared.global [%0], [%1], 16;"
                 :: "r"(dst), "l"(src));
}
__device__ __forceinline__ void cp_commit() {
    asm volatile("cp.async.commit_group;");
}
__device__ __forceinline__ void cp_wait1() {
    asm volatile("cp.async.wait_group 1;");
}
__device__ __forceinline__ void ldsm4(uint32_t* r, uint32_t addr) {
    asm volatile("ldmatrix.sync.aligned.m8n8.x4.shared.b16 {%0,%1,%2,%3}, [%4];"
                 : "=r"(r[0]), "=r"(r[1]), "=r"(r[2]), "=r"(r[3]) : "r"(addr));
}
__device__ __forceinline__ void ldsm4t(uint32_t* r, uint32_t addr) {
    asm volatile("ldmatrix.sync.aligned.m8n8.x4.trans.shared.b16 {%0,%1,%2,%3}, [%4];"
                 : "=r"(r[0]), "=r"(r[1]), "=r"(r[2]), "=r"(r[3]) : "r"(addr));
}
__device__ __forceinline__ void mma16816(float* c, const uint32_t* a,
                                         uint32_t b0, uint32_t b1) {
    asm volatile(
        "mma.sync.aligned.m16n8k16.row.col.f32.f16.f16.f32 "
        "{%0,%1,%2,%3}, {%4,%5,%6,%7}, {%8,%9}, {%0,%1,%2,%3};"
        : "+f"(c[0]), "+f"(c[1]), "+f"(c[2]), "+f"(c[3])
        : "r"(a[0]), "r"(a[1]), "r"(a[2]), "r"(a[3]), "r"(b0), "r"(b1));
}

// ============================ Kernel 1: bias ============================
__global__ void __launch_bounds__(128)
bias_kernel(const float* __restrict__ mlp_mask,
            const float* __restrict__ attn_mask,
            const float* __restrict__ modal_mlp,
            const float* __restrict__ modal_attention,
            const float* __restrict__ post_bias) {
    int b = blockIdx.x;
    int d = blockIdx.y * 128 + threadIdx.x;
    float acc = 0.f;
#pragma unroll
    for (int m = 0; m < Mm; m++)
        acc += (1.f - mlp_mask[b * Mm + m]) * modal_mlp[m * Dd + d];
#pragma unroll 4
    for (int ph = 0; ph < PH; ph++)
        acc += (1.f - attn_mask[b * PH + ph]) * modal_attention[ph * Dd + d];
#pragma unroll
    for (int p = 0; p < Ll; p++)
        acc += post_bias[p * Dd + d];
    g_bias[b * Dd + d] = acc;
}

// ============================ Kernel 2: W_O -> fp16 ============================
__global__ void __launch_bounds__(256)
prep_w(const float* __restrict__ Wo) {
    size_t i = (size_t)blockIdx.x * 256 + threadIdx.x;
    float4 v = reinterpret_cast<const float4*>(Wo)[i];
    __half2* dst = reinterpret_cast<__half2*>(g_Wh);
    dst[i * 2]     = __floats2half2_rn(v.x, v.y);
    dst[i * 2 + 1] = __floats2half2_rn(v.z, v.w);
}

// ============================ Kernel 3: A mask-scale -> fp16 ============================
__global__ void __launch_bounds__(256)
prep_a(const float* __restrict__ attn_stack, const float* __restrict__ attn_mask) {
    __shared__ float sM[PH];
    int bs = blockIdx.x;
    int b  = bs >> 9;
    int t  = threadIdx.x;
    if (t < PH) sM[t] = attn_mask[b * PH + t];
    __syncthreads();
    const float4* src = reinterpret_cast<const float4*>(attn_stack + (size_t)bs * GK);
    __half2* dst = reinterpret_cast<__half2*>(g_Ah + (size_t)bs * GK);
#pragma unroll
    for (int i = 0; i < 9; i++) {
        int idx = t + 256 * i;
        float s = sM[idx >> 4];
        float4 v = src[idx];
        dst[idx * 2]     = __floats2half2_rn(v.x * s, v.y * s);
        dst[idx * 2 + 1] = __floats2half2_rn(v.z * s, v.w * s);
    }
}

// ============================ Kernel 4: mlp term -> scratch ============================
__global__ void __launch_bounds__(192)
mlp_kernel(const float* __restrict__ mlp_stack,
           const float* __restrict__ mlp_mask) {
    int bs = blockIdx.x;
    int b  = bs >> 9;
    int t  = threadIdx.x;
    const float4* mp =
        reinterpret_cast<const float4*>(mlp_stack) + (size_t)bs * Mm * (Dd / 4);
    float4 acc = reinterpret_cast<const float4*>(g_bias)[b * (Dd / 4) + t];
#pragma unroll
    for (int m = 0; m < Mm; m++) {
        float w  = __ldg(&mlp_mask[b * Mm + m]);
        float4 v = mp[m * (Dd / 4) + t];
        acc.x += w * v.x; acc.y += w * v.y;
        acc.z += w * v.z; acc.w += w * v.w;
    }
    reinterpret_cast<float4*>(g_mlpout)[(size_t)bs * (Dd / 4) + t] = acc;
}

// ============================ Kernel 5: fp16 mma.sync GEMM ============================
// out[M,N] = g_Ah[M,K] @ g_Wh[K,N] + g_mlpout[M,N]
// 256 threads = 8 warps (2x4), 64x32 warp tiles, 2 CTAs/SM.
// ks-pipelined fragments: bf double-buffered, af 2-deep ring over mi.
__global__ void __launch_bounds__(256, 2)
attn_gemm(float* __restrict__ out) {
    extern __shared__ char smem[];
    const uint32_t s0 = smem_u32(smem);

    const int t    = threadIdx.x;
    const int lane = t & 31;
    const int wid  = t >> 5;
    const int wm   = wid >> 2;       // 0..1
    const int wn   = wid & 3;        // 0..3
    const int mRow0 = blockIdx.y * BM;
    const int nCol0 = blockIdx.x * BN;

    const __half* gA = g_Ah + (size_t)(mRow0 + (t >> 3)) * GK + (t & 7) * 8;
    const uint32_t sAw = s0 + (t >> 3) * (LDA_H * 2) + (t & 7) * 16;
    const __half* gB = g_Wh + (size_t)(t >> 4) * GN + nCol0 + (t & 15) * 8;
    const uint32_t sBw = s0 + SA_BYTES + (t >> 4) * (LDB_H * 2) + (t & 15) * 16;

    auto load_stage = [&](int kt, int st) {
        uint32_t so = st * STAGE_BYTES;
        const __half* ga = gA + kt * BK;
#pragma unroll
        for (int i = 0; i < 4; i++)
            cpasync16(sAw + so + i * 32 * (LDA_H * 2), ga + (size_t)i * 32 * GK);
        const __half* gb = gB + (size_t)kt * BK * GN;
#pragma unroll
        for (int i = 0; i < 4; i++)
            cpasync16(sBw + so + i * 16 * (LDB_H * 2), gb + (size_t)i * 16 * GN);
        cp_commit();
    };

    const uint32_t aBase = s0 + (wm * 64 + (lane & 15)) * (LDA_H * 2) + (lane >> 4) * 16;
    const uint32_t bBase = s0 + SA_BYTES + (lane & 15) * (LDB_H * 2) + wn * 64 + (lane >> 4) * 16;

    float acc[4][4][4];
#pragma unroll
    for (int mi = 0; mi < 4; mi++)
#pragma unroll
        for (int nt = 0; nt < 4; nt++)
#pragma unroll
            for (int r = 0; r < 4; r++) acc[mi][nt][r] = 0.f;

    load_stage(0, 0);
    load_stage(1, 1);

    int st_c = 0;
    int st_l = 2;
    for (int kt = 0; kt < KIT; kt++) {
        cp_wait1();
        __syncthreads();
        if (kt + 2 < KIT) load_stage(kt + 2, st_l);
        else cp_commit();

        const uint32_t so = st_c * STAGE_BYTES;
        uint32_t af[2][4];   // 2-deep ring over mi
        uint32_t bf[2][8];   // double buffer over ks

        // prime bf for ks=0
        ldsm4t(&bf[0][0], bBase + so);
        ldsm4t(&bf[0][4], bBase + so + 32);
#pragma unroll
        for (int ks = 0; ks < 4; ks++) {
            const int cur = ks & 1, nxt = cur ^ 1;
            if (ks < 3) {   // prefetch next ks B frags
                ldsm4t(&bf[nxt][0], bBase + so + (ks + 1) * 16 * (LDB_H * 2));
                ldsm4t(&bf[nxt][4], bBase + so + (ks + 1) * 16 * (LDB_H * 2) + 32);
            }
            // prime af for mi=0
            ldsm4(af[0], aBase + so + ks * 32);
#pragma unroll
            for (int mi = 0; mi < 4; mi++) {
                if (mi < 3)   // prefetch next mi A frag
                    ldsm4(af[(mi + 1) & 1],
                          aBase + so + (mi + 1) * 16 * (LDA_H * 2) + ks * 32);
                const uint32_t* a = af[mi & 1];
#pragma unroll
                for (int nt = 0; nt < 4; nt++)
                    mma16816(acc[mi][nt], a,
                             bf[cur][(nt >> 1) * 4 + (nt & 1) * 2],
                             bf[cur][(nt >> 1) * 4 + (nt & 1) * 2 + 1]);
            }
        }
        st_c = (st_c == STAGES - 1) ? 0 : st_c + 1;
        st_l = (st_l == STAGES - 1) ? 0 : st_l + 1;
    }

    // ---- epilogue: out = acc + mlpout ----
    const int g  = lane >> 2;
    const int tq = lane & 3;
#pragma unroll
    for (int mi = 0; mi < 4; mi++) {
        int row0 = mRow0 + wm * 64 + mi * 16 + g;
#pragma unroll
        for (int nt = 0; nt < 4; nt++) {
            int col = nCol0 + wn * 32 + nt * 8 + tq * 2;
            float2 u0 = *reinterpret_cast<const float2*>(g_mlpout + (size_t)row0 * GN + col);
            float2 u1 = *reinterpret_cast<const float2*>(g_mlpout + (size_t)(row0 + 8) * GN + col);
            float2 v0, v1;
            v0.x = acc[mi][nt][0] + u0.x; v0.y = acc[mi][nt][1] + u0.y;
            v1.x = acc[mi][nt][2] + u1.x; v1.y = acc[mi][nt][3] + u1.y;
            *reinterpret_cast<float2*>(out + (size_t)row0 * GN + col)       = v0;
            *reinterpret_cast<float2*>(out + (size_t)(row0 + 8) * GN + col) = v1;
        }
    }
}

// ============================ launch ============================
static const float* find_in(void* const* d_in, const int* in_sizes, int n_in,
                            long long want) {
    for (int i = 0; i < n_in; i++)
        if ((long long)in_sizes[i] == want) return (const float*)d_in[i];
    return nullptr;
}

extern "C" void kernel_launch(void* const* d_in, const int* in_sizes, int n_in,
                              void* d_out, int out_size) {
    const float* mlp_stack       = find_in(d_in, in_sizes, n_in, (long long)Bb * Ss * Mm * Dd);
    const float* attn_stack      = find_in(d_in, in_sizes, n_in, (long long)Bb * Ss * Ll * Hh * DHh);
    const float* mlp_mask        = find_in(d_in, in_sizes, n_in, (long long)Bb * Mm);
    const float* attn_mask       = find_in(d_in, in_sizes, n_in, (long long)Bb * Ll * Hh);
    const float* modal_mlp       = find_in(d_in, in_sizes, n_in, (long long)Mm * Dd);
    const float* modal_attention = find_in(d_in, in_sizes, n_in, (long long)Ll * Hh * Dd);
    const float* W_O             = find_in(d_in, in_sizes, n_in, (long long)Ll * Hh * DHh * Dd);
    const float* post_bias       = find_in(d_in, in_sizes, n_in, (long long)Ll * Dd);
    float* out = (float*)d_out;

    static cudaStream_t s2 = nullptr;
    static cudaEvent_t evFork = nullptr, evJoin = nullptr;
    static bool inited = false;
    if (!inited) {
        cudaFuncSetAttribute(attn_gemm,
                             cudaFuncAttributeMaxDynamicSharedMemorySize, GEMM_DSMEM);
        cudaStreamCreateWithFlags(&s2, cudaStreamNonBlocking);
        cudaEventCreateWithFlags(&evFork, cudaEventDisableTiming);
        cudaEventCreateWithFlags(&evJoin, cudaEventDisableTiming);
        inited = true;
    }

    // main: bias -> (fork) -> prep_w -> prep_a -> (join) -> gemm(+mlpout)
    bias_kernel<<<dim3(Bb, Dd / 128), 128>>>(mlp_mask, attn_mask, modal_mlp,
                                             modal_attention, post_bias);
    cudaEventRecord(evFork, 0);
    cudaStreamWaitEvent(s2, evFork, 0);

    // side: mlp term into scratch (overlaps prep_w + prep_a)
    mlp_kernel<<<GM, Dd / 4, 0, s2>>>(mlp_stack, mlp_mask);
    cudaEventRecord(evJoin, s2);

    prep_w<<<(GK * GN / 4) / 256, 256>>>(W_O);
    prep_a<<<GM, 256>>>(attn_stack, attn_mask);

    cudaStreamWaitEvent(0, evJoin, 0);
    dim3 ggrid(GN / BN, GM / BM);   // (6, 64)
    attn_gemm<<<ggrid, 256, GEMM_DSMEM>>>(out);
}